// round 1
// baseline (speedup 1.0000x reference)
#include <cuda_runtime.h>
#include <cuda_bf16.h>

#define BATCH 4096
#define DIM   256
#define NNEG  32768

// Scratch (no allocations allowed in kernel_launch)
__device__ float g_rowsum[BATCH];
__device__ float g_colsum[BATCH];
__device__ float g_negsum[BATCH];
__device__ float g_diag[BATCH];
__device__ int   g_off[BATCH];

__device__ __forceinline__ float inv_tau(const float* log_tau) {
    float t = expf(log_tau[0]);
    t = fminf(fmaxf(t, 1e-4f), 1.0f);
    return 1.0f / t;
}

__global__ void zero_kernel() {
    int i = blockIdx.x * blockDim.x + threadIdx.x;
    if (i < BATCH) { g_rowsum[i] = 0.f; g_colsum[i] = 0.f; }
}

// Exclusive prefix sum of n_counts (4096 elems, one block of 1024 threads).
__global__ void scan_kernel(const int* __restrict__ counts) {
    __shared__ int part[1024];
    int tid  = threadIdx.x;
    int base = tid * 4;
    int c0 = counts[base + 0];
    int c1 = counts[base + 1];
    int c2 = counts[base + 2];
    int c3 = counts[base + 3];
    part[tid] = c0 + c1 + c2 + c3;
    __syncthreads();
    #pragma unroll
    for (int off = 1; off < 1024; off <<= 1) {
        int v = (tid >= off) ? part[tid - off] : 0;
        __syncthreads();
        part[tid] += v;
        __syncthreads();
    }
    int excl = (tid > 0) ? part[tid - 1] : 0;
    g_off[base + 0] = excl;
    g_off[base + 1] = excl + c0;
    g_off[base + 2] = excl + c0 + c1;
    g_off[base + 3] = excl + c0 + c1 + c2;
}

// Fused S = (q p^T)/tau tile GEMM + exp + row/col sum accumulation + diag capture.
// 128x128 tile per block, BK=16, 256 threads, 8x8 microtile.
__global__ __launch_bounds__(256, 2) void sim_kernel(
    const float* __restrict__ q, const float* __restrict__ p,
    const float* __restrict__ log_tau)
{
    __shared__ float As[16][128];
    __shared__ float Bs[16][128];
    __shared__ float rs_sh[128];
    __shared__ float cs_sh[128];

    int tid  = threadIdx.x;
    int tx   = tid & 15;
    int ty   = tid >> 4;
    int lane = tid & 31;
    int row0 = blockIdx.y * 128;
    int col0 = blockIdx.x * 128;

    if (tid < 128) cs_sh[tid] = 0.f;

    float acc[8][8];
    #pragma unroll
    for (int i = 0; i < 8; i++)
        #pragma unroll
        for (int j = 0; j < 8; j++) acc[i][j] = 0.f;

    const float* qg = q + (size_t)row0 * DIM;
    const float* pg = p + (size_t)col0 * DIM;

    for (int kt = 0; kt < DIM; kt += 16) {
        // Load 128x16 tiles of q (A) and p (B), transposed into smem.
        #pragma unroll
        for (int it = 0; it < 2; it++) {
            int l  = it * 256 + tid;
            int r  = l >> 2;          // 0..127
            int kc = (l & 3) << 2;    // 0,4,8,12
            float4 av = *(const float4*)(qg + (size_t)r * DIM + kt + kc);
            As[kc + 0][r] = av.x; As[kc + 1][r] = av.y;
            As[kc + 2][r] = av.z; As[kc + 3][r] = av.w;
            float4 bv = *(const float4*)(pg + (size_t)r * DIM + kt + kc);
            Bs[kc + 0][r] = bv.x; Bs[kc + 1][r] = bv.y;
            Bs[kc + 2][r] = bv.z; Bs[kc + 3][r] = bv.w;
        }
        __syncthreads();
        #pragma unroll
        for (int k = 0; k < 16; k++) {
            float a[8], b[8];
            *(float4*)&a[0] = *(const float4*)&As[k][ty * 8];
            *(float4*)&a[4] = *(const float4*)&As[k][ty * 8 + 4];
            *(float4*)&b[0] = *(const float4*)&Bs[k][tx * 8];
            *(float4*)&b[4] = *(const float4*)&Bs[k][tx * 8 + 4];
            #pragma unroll
            for (int i = 0; i < 8; i++)
                #pragma unroll
                for (int j = 0; j < 8; j++)
                    acc[i][j] = fmaf(a[i], b[j], acc[i][j]);
        }
        __syncthreads();
    }

    float scale = inv_tau(log_tau);
    float rsum[8], csum[8];
    #pragma unroll
    for (int i = 0; i < 8; i++) { rsum[i] = 0.f; csum[i] = 0.f; }

    #pragma unroll
    for (int i = 0; i < 8; i++) {
        int grow = row0 + ty * 8 + i;
        #pragma unroll
        for (int j = 0; j < 8; j++) {
            int gcol = col0 + tx * 8 + j;
            float v = acc[i][j] * scale;
            float e = __expf(v);
            rsum[i] += e;
            csum[j] += e;
            if (grow == gcol) g_diag[grow] = v;
        }
    }

    // rsum: reduce over tx (lane bits 0..3); each (ty,i) row has one writer.
    #pragma unroll
    for (int i = 0; i < 8; i++) {
        #pragma unroll
        for (int m = 1; m < 16; m <<= 1)
            rsum[i] += __shfl_xor_sync(0xffffffffu, rsum[i], m);
    }
    if ((lane & 15) == 0) {
        #pragma unroll
        for (int i = 0; i < 8; i++) rs_sh[ty * 8 + i] = rsum[i];
    }
    // csum: reduce over ty parity (lane bit 4), then 8 warps atomically combine.
    #pragma unroll
    for (int j = 0; j < 8; j++)
        csum[j] += __shfl_xor_sync(0xffffffffu, csum[j], 16);
    if (lane < 16) {
        #pragma unroll
        for (int j = 0; j < 8; j++) atomicAdd(&cs_sh[tx * 8 + j], csum[j]);
    }
    __syncthreads();

    if (tid < 128) atomicAdd(&g_rowsum[row0 + tid], rs_sh[tid]);
    else           atomicAdd(&g_colsum[col0 + tid - 128], cs_sh[tid - 128]);
}

// Ragged negatives: one block per query, one warp per negative (<=16).
__global__ void neg_kernel(const float* __restrict__ q,
                           const float* __restrict__ nem,
                           const int*   __restrict__ counts,
                           const float* __restrict__ log_tau)
{
    int i    = blockIdx.x;
    int w    = threadIdx.x >> 5;
    int lane = threadIdx.x & 31;
    int cnt  = counts[i];

    __shared__ float part[16];
    float e = 0.f;
    if (w < cnt) {
        int nidx = g_off[i] + w;
        const float4* qr = (const float4*)(q   + (size_t)i    * DIM);
        const float4* nr = (const float4*)(nem + (size_t)nidx * DIM);
        float4 q0 = qr[lane * 2], q1 = qr[lane * 2 + 1];
        float4 n0 = nr[lane * 2], n1 = nr[lane * 2 + 1];
        float dot = q0.x * n0.x + q0.y * n0.y + q0.z * n0.z + q0.w * n0.w
                  + q1.x * n1.x + q1.y * n1.y + q1.z * n1.z + q1.w * n1.w;
        #pragma unroll
        for (int m = 16; m >= 1; m >>= 1)
            dot += __shfl_xor_sync(0xffffffffu, dot, m);
        e = __expf(dot * inv_tau(log_tau));
    }
    if (lane == 0) part[w] = e;
    __syncthreads();
    if (threadIdx.x < 16) {
        float v = part[threadIdx.x];
        #pragma unroll
        for (int m = 8; m >= 1; m >>= 1)
            v += __shfl_xor_sync(0x0000ffffu, v, m);
        if (threadIdx.x == 0) g_negsum[i] = v;
    }
}

__global__ void finalize_kernel(float* __restrict__ out) {
    __shared__ float sh[256];
    int tid = threadIdx.x;
    float s = 0.f;
    for (int i = tid; i < BATCH; i += 256) {
        float d  = g_diag[i];
        float lq = logf(g_rowsum[i] + g_negsum[i]) - d;
        float lp = logf(g_colsum[i]) - d;
        s += 0.5f * (lq + lp);
    }
    sh[tid] = s;
    __syncthreads();
    #pragma unroll
    for (int off = 128; off >= 32; off >>= 1) {
        if (tid < off) sh[tid] += sh[tid + off];
        __syncthreads();
    }
    if (tid < 32) {
        float v = sh[tid];
        #pragma unroll
        for (int m = 16; m >= 1; m >>= 1)
            v += __shfl_xor_sync(0xffffffffu, v, m);
        if (tid == 0) out[0] = v / (float)BATCH;
    }
}

extern "C" void kernel_launch(void* const* d_in, const int* in_sizes, int n_in,
                              void* d_out, int out_size) {
    const float* q   = (const float*)d_in[0];
    const float* p   = (const float*)d_in[1];
    const float* nem = (const float*)d_in[2];
    const int*   cnt = (const int*)  d_in[3];
    const float* lt  = (const float*)d_in[4];
    float* out = (float*)d_out;

    zero_kernel<<<16, 256>>>();
    scan_kernel<<<1, 1024>>>(cnt);
    sim_kernel<<<dim3(32, 32), 256>>>(q, p, lt);
    neg_kernel<<<BATCH, 512>>>(q, nem, cnt, lt);
    finalize_kernel<<<1, 256>>>(out);
}

// round 3
// speedup vs baseline: 3.0671x; 3.0671x over previous
#include <cuda_runtime.h>
#include <cuda_bf16.h>
#include <cstdint>

#define BATCH 4096
#define DIM   256
#define NNEG  32768

// ---------------- scratch (device globals; no allocs allowed) ----------------
__device__ float g_rowsum[BATCH];
__device__ float g_colsum[BATCH];
__device__ float g_negsum[BATCH];
__device__ float g_diag[BATCH];
__device__ int   g_qid[NNEG];
__device__ __nv_bfloat16 g_qb[BATCH * DIM];
__device__ __nv_bfloat16 g_pb[BATCH * DIM];

__device__ __forceinline__ uint32_t smem_u32(const void* p) {
    uint32_t a;
    asm("{ .reg .u64 t; cvta.to.shared.u64 t, %1; cvt.u32.u64 %0, t; }" : "=r"(a) : "l"(p));
    return a;
}

__device__ __forceinline__ float inv_tau(const float* log_tau) {
    float t = expf(log_tau[0]);
    t = fminf(fmaxf(t, 1e-4f), 1.0f);
    return 1.0f / t;
}

// ---------------- setup kernels ----------------
__global__ void zero_kernel() {
    int i = blockIdx.x * blockDim.x + threadIdx.x;
    if (i < BATCH) { g_rowsum[i] = 0.f; g_colsum[i] = 0.f; g_negsum[i] = 0.f; }
}

__global__ void convert_kernel(const float* __restrict__ q, const float* __restrict__ p) {
    int i = blockIdx.x * blockDim.x + threadIdx.x;  // over BATCH*DIM/4
    const float4 qa = ((const float4*)q)[i];
    const float4 pa = ((const float4*)p)[i];
    __nv_bfloat162* qd = (__nv_bfloat162*)g_qb;
    __nv_bfloat162* pd = (__nv_bfloat162*)g_pb;
    qd[i * 2 + 0] = __floats2bfloat162_rn(qa.x, qa.y);
    qd[i * 2 + 1] = __floats2bfloat162_rn(qa.z, qa.w);
    pd[i * 2 + 0] = __floats2bfloat162_rn(pa.x, pa.y);
    pd[i * 2 + 1] = __floats2bfloat162_rn(pa.z, pa.w);
}

// Exclusive scan of counts + neg->query map
__global__ void scan_kernel(const int* __restrict__ counts) {
    __shared__ int part[1024];
    int tid  = threadIdx.x;
    int base = tid * 4;
    int c0 = counts[base + 0], c1 = counts[base + 1];
    int c2 = counts[base + 2], c3 = counts[base + 3];
    part[tid] = c0 + c1 + c2 + c3;
    __syncthreads();
    #pragma unroll
    for (int off = 1; off < 1024; off <<= 1) {
        int v = (tid >= off) ? part[tid - off] : 0;
        __syncthreads();
        part[tid] += v;
        __syncthreads();
    }
    int excl = (tid > 0) ? part[tid - 1] : 0;
    int o0 = excl, o1 = o0 + c0, o2 = o1 + c1, o3 = o2 + c2;
    for (int k = 0; k < c0; k++) g_qid[o0 + k] = base + 0;
    for (int k = 0; k < c1; k++) g_qid[o1 + k] = base + 1;
    for (int k = 0; k < c2; k++) g_qid[o2 + k] = base + 2;
    for (int k = 0; k < c3; k++) g_qid[o3 + k] = base + 3;
}

// ---------------- MMA-based fused sim kernel ----------------
// CTA: 128x128 tile, K=256 fully resident. 8 warps in a 4(M) x 2(N) grid,
// each warp computes a 32x64 subtile via mma.sync.m16n8k16 (bf16 -> fp32).
// SMEM rows padded to 528B for conflict-free ldmatrix.
#define ROW_STRIDE 528
#define A_OFF 0
#define B_OFF (128 * ROW_STRIDE)
#define SM_TOTAL (2 * 128 * ROW_STRIDE)

__global__ __launch_bounds__(256, 1)
void sim_mma_kernel(const float* __restrict__ log_tau)
{
    extern __shared__ char smem[];
    const uint32_t sb = smem_u32(smem);
    const int tid  = threadIdx.x;
    const int wid  = tid >> 5;
    const int lane = tid & 31;
    const int row0 = blockIdx.y * 128;
    const int col0 = blockIdx.x * 128;
    const int warpM = (wid >> 1) * 32;   // 0,32,64,96
    const int warpN = (wid & 1) * 64;    // 0,64

    // ---- gmem -> smem (bf16 rows, 512B data + 16B pad) ----
    {
        const uint4* qa = (const uint4*)(g_qb + (size_t)row0 * DIM);
        const uint4* pa = (const uint4*)(g_pb + (size_t)col0 * DIM);
        #pragma unroll
        for (int it = 0; it < 16; it++) {
            int idx = it * 256 + tid;
            int r = idx >> 5, c = idx & 31;
            *(uint4*)(smem + A_OFF + r * ROW_STRIDE + c * 16) = qa[r * 32 + c];
            *(uint4*)(smem + B_OFF + r * ROW_STRIDE + c * 16) = pa[r * 32 + c];
        }
    }
    __syncthreads();

    // ---- ldmatrix base addresses ----
    // A x4: lanes 0-15 -> rows (l%16) @byte 0..15 of kstep; lanes 16-31 same rows @byte16
    const uint32_t aAddr = sb + A_OFF
        + (uint32_t)(warpM + (lane & 15)) * ROW_STRIDE + (uint32_t)(lane >> 4) * 16;
    // B x4: lanes0-7 rows n0..7 @b0; 8-15 same rows @b16; 16-23 rows+8 @b0; 24-31 rows+8 @b16
    const uint32_t bAddr = sb + B_OFF
        + (uint32_t)(warpN + (lane & 7) + ((lane >> 4) << 3)) * ROW_STRIDE
        + (uint32_t)((lane >> 3) & 1) * 16;

    float acc[2][8][4];
    #pragma unroll
    for (int mi = 0; mi < 2; mi++)
        #pragma unroll
        for (int ni = 0; ni < 8; ni++)
            #pragma unroll
            for (int r = 0; r < 4; r++) acc[mi][ni][r] = 0.f;

    #pragma unroll
    for (int s = 0; s < 16; s++) {
        const uint32_t koff = (uint32_t)s * 32;
        uint32_t a[2][4];
        #pragma unroll
        for (int mi = 0; mi < 2; mi++) {
            asm volatile("ldmatrix.sync.aligned.m8n8.x4.shared.b16 {%0,%1,%2,%3}, [%4];"
                : "=r"(a[mi][0]), "=r"(a[mi][1]), "=r"(a[mi][2]), "=r"(a[mi][3])
                : "r"(aAddr + mi * (16 * ROW_STRIDE) + koff));
        }
        uint32_t b[4][4];
        #pragma unroll
        for (int nb = 0; nb < 4; nb++) {
            asm volatile("ldmatrix.sync.aligned.m8n8.x4.shared.b16 {%0,%1,%2,%3}, [%4];"
                : "=r"(b[nb][0]), "=r"(b[nb][1]), "=r"(b[nb][2]), "=r"(b[nb][3])
                : "r"(bAddr + nb * (16 * ROW_STRIDE) + koff));
        }
        #pragma unroll
        for (int mi = 0; mi < 2; mi++)
            #pragma unroll
            for (int nb = 0; nb < 4; nb++)
                #pragma unroll
                for (int sub = 0; sub < 2; sub++) {
                    float* d = acc[mi][nb * 2 + sub];
                    asm volatile(
                        "mma.sync.aligned.m16n8k16.row.col.f32.bf16.bf16.f32 "
                        "{%0,%1,%2,%3}, {%4,%5,%6,%7}, {%8,%9}, {%0,%1,%2,%3};"
                        : "+f"(d[0]), "+f"(d[1]), "+f"(d[2]), "+f"(d[3])
                        : "r"(a[mi][0]), "r"(a[mi][1]), "r"(a[mi][2]), "r"(a[mi][3]),
                          "r"(b[nb][sub * 2]), "r"(b[nb][sub * 2 + 1]));
                }
    }

    // ---- epilogue: scale, exp, row/col sums, diag ----
    // Fragment owner: g = lane>>2, tig = lane&3.
    //   d[0]: (row g,    col tig*2)   d[1]: (row g,    col tig*2+1)
    //   d[2]: (row g+8,  col tig*2)   d[3]: (row g+8,  col tig*2+1)
    const float scale = inv_tau(log_tau);
    const int g   = lane >> 2;
    const int tig = lane & 3;
    const bool diagBlk = (row0 == col0);

    float rsum[4];   // rows: warpM + mi*16 + h*8 + g  (idx = mi*2+h)
    #pragma unroll
    for (int k = 0; k < 4; k++) rsum[k] = 0.f;
    float csum[8][2];  // cols: warpN + ni*8 + tig*2 + c
    #pragma unroll
    for (int ni = 0; ni < 8; ni++) { csum[ni][0] = 0.f; csum[ni][1] = 0.f; }

    #pragma unroll
    for (int mi = 0; mi < 2; mi++)
        #pragma unroll
        for (int ni = 0; ni < 8; ni++)
            #pragma unroll
            for (int r = 0; r < 4; r++) {
                int h = r >> 1, c = r & 1;
                float v = acc[mi][ni][r] * scale;
                if (diagBlk) {
                    int lr = warpM + mi * 16 + h * 8 + g;
                    int lc = warpN + ni * 8 + tig * 2 + c;
                    if (lr == lc) g_diag[row0 + lr] = v;
                }
                float e = __expf(v);
                rsum[mi * 2 + h] += e;
                csum[ni][c] += e;
            }

    // reduce rsum over tig (lane bits 0-1)
    #pragma unroll
    for (int k = 0; k < 4; k++) {
        rsum[k] += __shfl_xor_sync(0xffffffffu, rsum[k], 1);
        rsum[k] += __shfl_xor_sync(0xffffffffu, rsum[k], 2);
    }
    if (tig == 0) {
        #pragma unroll
        for (int k = 0; k < 4; k++) {
            int lr = warpM + (k >> 1) * 16 + (k & 1) * 8 + g;
            atomicAdd(&g_rowsum[row0 + lr], rsum[k]);
        }
    }
    // reduce csum over g (lane bits 2-4)
    #pragma unroll
    for (int ni = 0; ni < 8; ni++)
        #pragma unroll
        for (int c = 0; c < 2; c++) {
            csum[ni][c] += __shfl_xor_sync(0xffffffffu, csum[ni][c], 4);
            csum[ni][c] += __shfl_xor_sync(0xffffffffu, csum[ni][c], 8);
            csum[ni][c] += __shfl_xor_sync(0xffffffffu, csum[ni][c], 16);
        }
    if (lane < 4) {
        #pragma unroll
        for (int ni = 0; ni < 8; ni++)
            #pragma unroll
            for (int c = 0; c < 2; c++) {
                int lc = warpN + ni * 8 + lane * 2 + c;
                atomicAdd(&g_colsum[col0 + lc], csum[ni][c]);
            }
    }
}

// ---------------- negatives: one warp per 2 negatives ----------------
__global__ __launch_bounds__(256) void neg_kernel(const float* __restrict__ q,
                                                  const float* __restrict__ nem,
                                                  const float* __restrict__ log_tau)
{
    int w    = blockIdx.x * 8 + (threadIdx.x >> 5);
    int g0   = w * 2;
    int lane = threadIdx.x & 31;
    int qa = g_qid[g0];
    int qb = g_qid[g0 + 1];

    const float4* nrA = (const float4*)(nem + (size_t)g0 * DIM);
    const float4* nrB = (const float4*)(nem + (size_t)(g0 + 1) * DIM);
    const float4* qrA = (const float4*)(q   + (size_t)qa * DIM);
    const float4* qrB = (const float4*)(q   + (size_t)qb * DIM);

    float4 nA0 = nrA[lane], nA1 = nrA[lane + 32];
    float4 nB0 = nrB[lane], nB1 = nrB[lane + 32];
    float4 qA0 = qrA[lane], qA1 = qrA[lane + 32];
    float4 qB0 = qrB[lane], qB1 = qrB[lane + 32];

    float dA = qA0.x * nA0.x + qA0.y * nA0.y + qA0.z * nA0.z + qA0.w * nA0.w
             + qA1.x * nA1.x + qA1.y * nA1.y + qA1.z * nA1.z + qA1.w * nA1.w;
    float dB = qB0.x * nB0.x + qB0.y * nB0.y + qB0.z * nB0.z + qB0.w * nB0.w
             + qB1.x * nB1.x + qB1.y * nB1.y + qB1.z * nB1.z + qB1.w * nB1.w;
    #pragma unroll
    for (int m = 16; m >= 1; m >>= 1) {
        dA += __shfl_xor_sync(0xffffffffu, dA, m);
        dB += __shfl_xor_sync(0xffffffffu, dB, m);
    }
    if (lane == 0) {
        float s = inv_tau(log_tau);
        atomicAdd(&g_negsum[qa], __expf(dA * s));
        atomicAdd(&g_negsum[qb], __expf(dB * s));
    }
}

// ---------------- finalize ----------------
__global__ void finalize_kernel(float* __restrict__ out) {
    __shared__ float sh[256];
    int tid = threadIdx.x;
    float s = 0.f;
    for (int i = tid; i < BATCH; i += 256) {
        float d  = g_diag[i];
        float lq = logf(g_rowsum[i] + g_negsum[i]) - d;
        float lp = logf(g_colsum[i]) - d;
        s += 0.5f * (lq + lp);
    }
    sh[tid] = s;
    __syncthreads();
    #pragma unroll
    for (int off = 128; off >= 32; off >>= 1) {
        if (tid < off) sh[tid] += sh[tid + off];
        __syncthreads();
    }
    if (tid < 32) {
        float v = sh[tid];
        #pragma unroll
        for (int m = 16; m >= 1; m >>= 1)
            v += __shfl_xor_sync(0xffffffffu, v, m);
        if (tid == 0) out[0] = v / (float)BATCH;
    }
}

extern "C" void kernel_launch(void* const* d_in, const int* in_sizes, int n_in,
                              void* d_out, int out_size) {
    const float* q   = (const float*)d_in[0];
    const float* p   = (const float*)d_in[1];
    const float* nem = (const float*)d_in[2];
    const int*   cnt = (const int*)  d_in[3];
    const float* lt  = (const float*)d_in[4];
    float* out = (float*)d_out;

    cudaFuncSetAttribute(sim_mma_kernel,
                         cudaFuncAttributeMaxDynamicSharedMemorySize, SM_TOTAL);

    zero_kernel<<<16, 256>>>();
    convert_kernel<<<BATCH * DIM / 4 / 256, 256>>>(q, p);
    scan_kernel<<<1, 1024>>>(cnt);
    sim_mma_kernel<<<dim3(32, 32), 256, SM_TOTAL>>>(lt);
    neg_kernel<<<NNEG / 16, 256>>>(q, nem, lt);
    finalize_kernel<<<1, 256>>>(out);
}

// round 4
// speedup vs baseline: 3.4539x; 1.1261x over previous
#include <cuda_runtime.h>
#include <cuda_bf16.h>
#include <cstdint>

#define BATCH 4096
#define DIM   256
#define NNEG  32768

// ---------------- scratch (device globals; no allocs allowed) ----------------
__device__ float g_rowsum[BATCH];
__device__ float g_colsum[BATCH];
__device__ float g_negsum[BATCH];
__device__ float g_diag[BATCH];
__device__ int   g_qid[NNEG];
__device__ __nv_bfloat16 g_qb[BATCH * DIM];
__device__ __nv_bfloat16 g_pb[BATCH * DIM];

__device__ __forceinline__ uint32_t smem_u32(const void* p) {
    uint32_t a;
    asm("{ .reg .u64 t; cvta.to.shared.u64 t, %1; cvt.u32.u64 %0, t; }" : "=r"(a) : "l"(p));
    return a;
}

__device__ __forceinline__ float inv_tau(const float* log_tau) {
    float t = expf(log_tau[0]);
    t = fminf(fmaxf(t, 1e-4f), 1.0f);
    return 1.0f / t;
}

// ---------------- setup: fp32 -> bf16 convert + zero accumulators ----------------
__global__ void convert_kernel(const float* __restrict__ q, const float* __restrict__ p) {
    int i = blockIdx.x * blockDim.x + threadIdx.x;  // over BATCH*DIM/4
    if (i < BATCH) { g_rowsum[i] = 0.f; g_colsum[i] = 0.f; g_negsum[i] = 0.f; }
    const float4 qa = ((const float4*)q)[i];
    const float4 pa = ((const float4*)p)[i];
    __nv_bfloat162* qd = (__nv_bfloat162*)g_qb;
    __nv_bfloat162* pd = (__nv_bfloat162*)g_pb;
    qd[i * 2 + 0] = __floats2bfloat162_rn(qa.x, qa.y);
    qd[i * 2 + 1] = __floats2bfloat162_rn(qa.z, qa.w);
    pd[i * 2 + 0] = __floats2bfloat162_rn(pa.x, pa.y);
    pd[i * 2 + 1] = __floats2bfloat162_rn(pa.z, pa.w);
}

// Exclusive scan of counts + neg->query map
__global__ void scan_kernel(const int* __restrict__ counts) {
    __shared__ int part[1024];
    int tid  = threadIdx.x;
    int base = tid * 4;
    int c0 = counts[base + 0], c1 = counts[base + 1];
    int c2 = counts[base + 2], c3 = counts[base + 3];
    part[tid] = c0 + c1 + c2 + c3;
    __syncthreads();
    #pragma unroll
    for (int off = 1; off < 1024; off <<= 1) {
        int v = (tid >= off) ? part[tid - off] : 0;
        __syncthreads();
        part[tid] += v;
        __syncthreads();
    }
    int excl = (tid > 0) ? part[tid - 1] : 0;
    int o0 = excl, o1 = o0 + c0, o2 = o1 + c1, o3 = o2 + c2;
    for (int k = 0; k < c0; k++) g_qid[o0 + k] = base + 0;
    for (int k = 0; k < c1; k++) g_qid[o1 + k] = base + 1;
    for (int k = 0; k < c2; k++) g_qid[o2 + k] = base + 2;
    for (int k = 0; k < c3; k++) g_qid[o3 + k] = base + 3;
}

// ---------------- MMA-based fused sim kernel (cp.async pipelined) ----------------
// CTA: 128x128 tile. K=256 split into 4 chunks of 64, double-buffered.
// 8 warps in 4(M) x 2(N) grid; each warp computes 32x64 via mma.m16n8k16.
// Chunk rows are 128B data @ stride 144 -> ldmatrix conflict-free
// (row i starts at bank 4i mod 32; any 8 consecutive rows cover all banks).
#define STRIDE     144
#define TILE_BYTES (128 * STRIDE)      // 18432 per operand per chunk
#define BUF_BYTES  (2 * TILE_BYTES)    // A then B
#define SM_TOTAL   (2 * BUF_BYTES)     // 73728 (2 buffers)

#define CP_COMMIT() asm volatile("cp.async.commit_group;" ::: "memory")

__device__ __forceinline__ void load_chunk(uint32_t sb, const char* qa, const char* pa,
                                           int chunk, int buf, int tid) {
    uint32_t base = sb + buf * BUF_BYTES;
    #pragma unroll
    for (int it = 0; it < 4; it++) {
        int idx = it * 256 + tid;          // 0..1023
        int r = idx >> 3, s = idx & 7;     // row, 16B segment
        uint32_t dst = base + r * STRIDE + s * 16;
        const char* srcA = qa + r * 512 + chunk * 128 + s * 16;
        const char* srcB = pa + r * 512 + chunk * 128 + s * 16;
        asm volatile("cp.async.cg.shared.global [%0], [%1], 16;" :: "r"(dst), "l"(srcA));
        asm volatile("cp.async.cg.shared.global [%0], [%1], 16;"
                     :: "r"(dst + TILE_BYTES), "l"(srcB));
    }
}

__device__ __forceinline__ void compute_chunk(uint32_t sb, int buf, int warpM, int warpN,
                                              int lane, float acc[2][8][4]) {
    uint32_t base  = sb + buf * BUF_BYTES;
    uint32_t aAddr = base + (uint32_t)(warpM + (lane & 15)) * STRIDE
                   + (uint32_t)(lane >> 4) * 16;
    uint32_t bAddr = base + TILE_BYTES
                   + (uint32_t)(warpN + (lane & 7) + ((lane >> 4) << 3)) * STRIDE
                   + (uint32_t)((lane >> 3) & 1) * 16;
    #pragma unroll
    for (int s = 0; s < 4; s++) {
        const uint32_t koff = (uint32_t)s * 32;
        uint32_t a[2][4];
        #pragma unroll
        for (int mi = 0; mi < 2; mi++) {
            asm volatile("ldmatrix.sync.aligned.m8n8.x4.shared.b16 {%0,%1,%2,%3}, [%4];"
                : "=r"(a[mi][0]), "=r"(a[mi][1]), "=r"(a[mi][2]), "=r"(a[mi][3])
                : "r"(aAddr + mi * (16 * STRIDE) + koff));
        }
        uint32_t b[4][4];
        #pragma unroll
        for (int nb = 0; nb < 4; nb++) {
            asm volatile("ldmatrix.sync.aligned.m8n8.x4.shared.b16 {%0,%1,%2,%3}, [%4];"
                : "=r"(b[nb][0]), "=r"(b[nb][1]), "=r"(b[nb][2]), "=r"(b[nb][3])
                : "r"(bAddr + nb * (16 * STRIDE) + koff));
        }
        #pragma unroll
        for (int mi = 0; mi < 2; mi++)
            #pragma unroll
            for (int nb = 0; nb < 4; nb++)
                #pragma unroll
                for (int sub = 0; sub < 2; sub++) {
                    float* d = acc[mi][nb * 2 + sub];
                    asm volatile(
                        "mma.sync.aligned.m16n8k16.row.col.f32.bf16.bf16.f32 "
                        "{%0,%1,%2,%3}, {%4,%5,%6,%7}, {%8,%9}, {%0,%1,%2,%3};"
                        : "+f"(d[0]), "+f"(d[1]), "+f"(d[2]), "+f"(d[3])
                        : "r"(a[mi][0]), "r"(a[mi][1]), "r"(a[mi][2]), "r"(a[mi][3]),
                          "r"(b[nb][sub * 2]), "r"(b[nb][sub * 2 + 1]));
                }
    }
}

__global__ __launch_bounds__(256, 2)
void sim_mma_kernel(const float* __restrict__ log_tau)
{
    extern __shared__ char smem[];
    const uint32_t sb = smem_u32(smem);
    const int tid  = threadIdx.x;
    const int wid  = tid >> 5;
    const int lane = tid & 31;
    const int row0 = blockIdx.y * 128;
    const int col0 = blockIdx.x * 128;
    const int warpM = (wid >> 1) * 32;   // 0,32,64,96
    const int warpN = (wid & 1) * 64;    // 0,64

    const char* qa = (const char*)(g_qb + (size_t)row0 * DIM);
    const char* pa = (const char*)(g_pb + (size_t)col0 * DIM);

    float acc[2][8][4];
    #pragma unroll
    for (int mi = 0; mi < 2; mi++)
        #pragma unroll
        for (int ni = 0; ni < 8; ni++)
            #pragma unroll
            for (int r = 0; r < 4; r++) acc[mi][ni][r] = 0.f;

    // ---- software pipeline: 4 chunks, 2-stage ----
    load_chunk(sb, qa, pa, 0, 0, tid); CP_COMMIT();
    load_chunk(sb, qa, pa, 1, 1, tid); CP_COMMIT();

    asm volatile("cp.async.wait_group 1;" ::: "memory");
    __syncthreads();
    compute_chunk(sb, 0, warpM, warpN, lane, acc);
    __syncthreads();
    load_chunk(sb, qa, pa, 2, 0, tid); CP_COMMIT();

    asm volatile("cp.async.wait_group 1;" ::: "memory");
    __syncthreads();
    compute_chunk(sb, 1, warpM, warpN, lane, acc);
    __syncthreads();
    load_chunk(sb, qa, pa, 3, 1, tid); CP_COMMIT();

    asm volatile("cp.async.wait_group 1;" ::: "memory");
    __syncthreads();
    compute_chunk(sb, 0, warpM, warpN, lane, acc);

    asm volatile("cp.async.wait_group 0;" ::: "memory");
    __syncthreads();
    compute_chunk(sb, 1, warpM, warpN, lane, acc);

    // ---- epilogue: scale, exp, row/col sums, diag ----
    // Fragment owner: g = lane>>2, tig = lane&3.
    //   d[0]: (row g, col tig*2)  d[1]: (row g, col tig*2+1)
    //   d[2]: (row g+8, ...)      d[3]: (row g+8, ...)
    const float scale = inv_tau(log_tau);
    const int g   = lane >> 2;
    const int tig = lane & 3;
    const bool diagBlk = (row0 == col0);

    float rsum[4];
    #pragma unroll
    for (int k = 0; k < 4; k++) rsum[k] = 0.f;
    float csum[8][2];
    #pragma unroll
    for (int ni = 0; ni < 8; ni++) { csum[ni][0] = 0.f; csum[ni][1] = 0.f; }

    #pragma unroll
    for (int mi = 0; mi < 2; mi++)
        #pragma unroll
        for (int ni = 0; ni < 8; ni++)
            #pragma unroll
            for (int r = 0; r < 4; r++) {
                int h = r >> 1, c = r & 1;
                float v = acc[mi][ni][r] * scale;
                if (diagBlk) {
                    int lr = warpM + mi * 16 + h * 8 + g;
                    int lc = warpN + ni * 8 + tig * 2 + c;
                    if (lr == lc) g_diag[row0 + lr] = v;
                }
                float e = __expf(v);
                rsum[mi * 2 + h] += e;
                csum[ni][c] += e;
            }

    #pragma unroll
    for (int k = 0; k < 4; k++) {
        rsum[k] += __shfl_xor_sync(0xffffffffu, rsum[k], 1);
        rsum[k] += __shfl_xor_sync(0xffffffffu, rsum[k], 2);
    }
    if (tig == 0) {
        #pragma unroll
        for (int k = 0; k < 4; k++) {
            int lr = warpM + (k >> 1) * 16 + (k & 1) * 8 + g;
            atomicAdd(&g_rowsum[row0 + lr], rsum[k]);
        }
    }
    #pragma unroll
    for (int ni = 0; ni < 8; ni++)
        #pragma unroll
        for (int c = 0; c < 2; c++) {
            csum[ni][c] += __shfl_xor_sync(0xffffffffu, csum[ni][c], 4);
            csum[ni][c] += __shfl_xor_sync(0xffffffffu, csum[ni][c], 8);
            csum[ni][c] += __shfl_xor_sync(0xffffffffu, csum[ni][c], 16);
        }
    if (lane < 4) {
        #pragma unroll
        for (int ni = 0; ni < 8; ni++)
            #pragma unroll
            for (int c = 0; c < 2; c++) {
                int lc = warpN + ni * 8 + lane * 2 + c;
                atomicAdd(&g_colsum[col0 + lc], csum[ni][c]);
            }
    }
}

// ---------------- negatives: one warp per 4 negatives (MLP 16) ----------------
__global__ __launch_bounds__(256) void neg_kernel(const float* __restrict__ q,
                                                  const float* __restrict__ nem,
                                                  const float* __restrict__ log_tau)
{
    int w    = blockIdx.x * 8 + (threadIdx.x >> 5);
    int g0   = w * 4;
    int lane = threadIdx.x & 31;

    int qid[4];
    float4 nv[4][2], qv[4][2];
    #pragma unroll
    for (int k = 0; k < 4; k++) {
        qid[k] = g_qid[g0 + k];
        const float4* nr = (const float4*)(nem + (size_t)(g0 + k) * DIM);
        nv[k][0] = nr[lane]; nv[k][1] = nr[lane + 32];
    }
    #pragma unroll
    for (int k = 0; k < 4; k++) {
        const float4* qr = (const float4*)(q + (size_t)qid[k] * DIM);
        qv[k][0] = qr[lane]; qv[k][1] = qr[lane + 32];
    }
    float dot[4];
    #pragma unroll
    for (int k = 0; k < 4; k++) {
        dot[k] = qv[k][0].x * nv[k][0].x + qv[k][0].y * nv[k][0].y
               + qv[k][0].z * nv[k][0].z + qv[k][0].w * nv[k][0].w
               + qv[k][1].x * nv[k][1].x + qv[k][1].y * nv[k][1].y
               + qv[k][1].z * nv[k][1].z + qv[k][1].w * nv[k][1].w;
    }
    #pragma unroll
    for (int m = 16; m >= 1; m >>= 1) {
        #pragma unroll
        for (int k = 0; k < 4; k++)
            dot[k] += __shfl_xor_sync(0xffffffffu, dot[k], m);
    }
    if (lane == 0) {
        float s = inv_tau(log_tau);
        #pragma unroll
        for (int k = 0; k < 4; k++)
            atomicAdd(&g_negsum[qid[k]], __expf(dot[k] * s));
    }
}

// ---------------- finalize ----------------
__global__ void finalize_kernel(float* __restrict__ out) {
    __shared__ float sh[256];
    int tid = threadIdx.x;
    float s = 0.f;
    for (int i = tid; i < BATCH; i += 256) {
        float d  = g_diag[i];
        float lq = logf(g_rowsum[i] + g_negsum[i]) - d;
        float lp = logf(g_colsum[i]) - d;
        s += 0.5f * (lq + lp);
    }
    sh[tid] = s;
    __syncthreads();
    #pragma unroll
    for (int off = 128; off >= 32; off >>= 1) {
        if (tid < off) sh[tid] += sh[tid + off];
        __syncthreads();
    }
    if (tid < 32) {
        float v = sh[tid];
        #pragma unroll
        for (int m = 16; m >= 1; m >>= 1)
            v += __shfl_xor_sync(0xffffffffu, v, m);
        if (tid == 0) out[0] = v / (float)BATCH;
    }
}

extern "C" void kernel_launch(void* const* d_in, const int* in_sizes, int n_in,
                              void* d_out, int out_size) {
    const float* q   = (const float*)d_in[0];
    const float* p   = (const float*)d_in[1];
    const float* nem = (const float*)d_in[2];
    const int*   cnt = (const int*)  d_in[3];
    const float* lt  = (const float*)d_in[4];
    float* out = (float*)d_out;

    cudaFuncSetAttribute(sim_mma_kernel,
                         cudaFuncAttributeMaxDynamicSharedMemorySize, SM_TOTAL);

    convert_kernel<<<BATCH * DIM / 4 / 256, 256>>>(q, p);
    scan_kernel<<<1, 1024>>>(cnt);
    sim_mma_kernel<<<dim3(32, 32), 256, SM_TOTAL>>>(lt);
    neg_kernel<<<NNEG / 32, 256>>>(q, nem, lt);
    finalize_kernel<<<1, 256>>>(out);
}

// round 5
// speedup vs baseline: 3.5426x; 1.0257x over previous
#include <cuda_runtime.h>
#include <cuda_bf16.h>
#include <cstdint>

#define BATCH 4096
#define DIM   256
#define NNEG  32768

// ---------------- scratch (device globals; no allocs allowed) ----------------
__device__ float g_rowsum[BATCH];
__device__ float g_colsum[BATCH];
__device__ float g_negsum[BATCH];
__device__ float g_diag[BATCH];
__device__ int   g_qid[NNEG];
__device__ __nv_bfloat16 g_qb[BATCH * DIM];
__device__ __nv_bfloat16 g_pb[BATCH * DIM];

__device__ __forceinline__ uint32_t smem_u32(const void* p) {
    uint32_t a;
    asm("{ .reg .u64 t; cvta.to.shared.u64 t, %1; cvt.u32.u64 %0, t; }" : "=r"(a) : "l"(p));
    return a;
}

__device__ __forceinline__ float inv_tau(const float* log_tau) {
    float t = expf(log_tau[0]);
    t = fminf(fmaxf(t, 1e-4f), 1.0f);
    return 1.0f / t;
}

// ---------------- setup: fp32->bf16 convert + zero + (block 1024) scan ----------------
__global__ void convert_scan_kernel(const float* __restrict__ q, const float* __restrict__ p,
                                    const int* __restrict__ counts) {
    int tid = threadIdx.x;
    if (blockIdx.x < 1024) {
        int i = blockIdx.x * 256 + tid;  // over BATCH*DIM/4
        if (i < BATCH) { g_rowsum[i] = 0.f; g_colsum[i] = 0.f; g_negsum[i] = 0.f; }
        const float4 qa = ((const float4*)q)[i];
        const float4 pa = ((const float4*)p)[i];
        __nv_bfloat162* qd = (__nv_bfloat162*)g_qb;
        __nv_bfloat162* pd = (__nv_bfloat162*)g_pb;
        qd[i * 2 + 0] = __floats2bfloat162_rn(qa.x, qa.y);
        qd[i * 2 + 1] = __floats2bfloat162_rn(qa.z, qa.w);
        pd[i * 2 + 0] = __floats2bfloat162_rn(pa.x, pa.y);
        pd[i * 2 + 1] = __floats2bfloat162_rn(pa.z, pa.w);
        return;
    }
    // ---- scan block: exclusive scan of counts + neg->query map ----
    __shared__ int wsum[8];
    int lane = tid & 31, w = tid >> 5;
    int base = tid * 16;
    int c[16], loc[16];
    int run = 0;
    #pragma unroll
    for (int k = 0; k < 16; k++) {
        c[k] = counts[base + k];
        loc[k] = run;
        run += c[k];
    }
    int incl = run;
    #pragma unroll
    for (int m = 1; m < 32; m <<= 1) {
        int t = __shfl_up_sync(0xffffffffu, incl, m);
        if (lane >= m) incl += t;
    }
    if (lane == 31) wsum[w] = incl;
    __syncthreads();
    if (tid == 0) {
        int s = 0;
        #pragma unroll
        for (int i = 0; i < 8; i++) { int t = wsum[i]; wsum[i] = s; s += t; }
    }
    __syncthreads();
    int excl = incl - run + wsum[w];
    #pragma unroll
    for (int k = 0; k < 16; k++) {
        int o = excl + loc[k];
        for (int j = 0; j < c[k]; j++) g_qid[o + j] = base + k;
    }
}

// ---------------- fused sim(MMA) + neg kernel ----------------
// Even blockIdx -> sim 128x128 tile; odd blockIdx -> 32 negatives.
#define STRIDE     144
#define TILE_BYTES (128 * STRIDE)
#define BUF_BYTES  (2 * TILE_BYTES)
#define SM_TOTAL   (2 * BUF_BYTES)     // 73728

#define CP_COMMIT() asm volatile("cp.async.commit_group;" ::: "memory")

__device__ __forceinline__ void load_chunk(uint32_t sb, const char* qa, const char* pa,
                                           int chunk, int buf, int tid) {
    uint32_t base = sb + buf * BUF_BYTES;
    #pragma unroll
    for (int it = 0; it < 4; it++) {
        int idx = it * 256 + tid;
        int r = idx >> 3, s = idx & 7;
        uint32_t dst = base + r * STRIDE + s * 16;
        const char* srcA = qa + r * 512 + chunk * 128 + s * 16;
        const char* srcB = pa + r * 512 + chunk * 128 + s * 16;
        asm volatile("cp.async.cg.shared.global [%0], [%1], 16;" :: "r"(dst), "l"(srcA));
        asm volatile("cp.async.cg.shared.global [%0], [%1], 16;"
                     :: "r"(dst + TILE_BYTES), "l"(srcB));
    }
}

__device__ __forceinline__ void compute_chunk(uint32_t sb, int buf, int warpM, int warpN,
                                              int lane, float acc[2][8][4]) {
    uint32_t base  = sb + buf * BUF_BYTES;
    uint32_t aAddr = base + (uint32_t)(warpM + (lane & 15)) * STRIDE
                   + (uint32_t)(lane >> 4) * 16;
    uint32_t bAddr = base + TILE_BYTES
                   + (uint32_t)(warpN + (lane & 7) + ((lane >> 4) << 3)) * STRIDE
                   + (uint32_t)((lane >> 3) & 1) * 16;
    #pragma unroll
    for (int s = 0; s < 4; s++) {
        const uint32_t koff = (uint32_t)s * 32;
        uint32_t a[2][4];
        #pragma unroll
        for (int mi = 0; mi < 2; mi++) {
            asm volatile("ldmatrix.sync.aligned.m8n8.x4.shared.b16 {%0,%1,%2,%3}, [%4];"
                : "=r"(a[mi][0]), "=r"(a[mi][1]), "=r"(a[mi][2]), "=r"(a[mi][3])
                : "r"(aAddr + mi * (16 * STRIDE) + koff));
        }
        uint32_t b[4][4];
        #pragma unroll
        for (int nb = 0; nb < 4; nb++) {
            asm volatile("ldmatrix.sync.aligned.m8n8.x4.shared.b16 {%0,%1,%2,%3}, [%4];"
                : "=r"(b[nb][0]), "=r"(b[nb][1]), "=r"(b[nb][2]), "=r"(b[nb][3])
                : "r"(bAddr + nb * (16 * STRIDE) + koff));
        }
        #pragma unroll
        for (int mi = 0; mi < 2; mi++)
            #pragma unroll
            for (int nb = 0; nb < 4; nb++)
                #pragma unroll
                for (int sub = 0; sub < 2; sub++) {
                    float* d = acc[mi][nb * 2 + sub];
                    asm volatile(
                        "mma.sync.aligned.m16n8k16.row.col.f32.bf16.bf16.f32 "
                        "{%0,%1,%2,%3}, {%4,%5,%6,%7}, {%8,%9}, {%0,%1,%2,%3};"
                        : "+f"(d[0]), "+f"(d[1]), "+f"(d[2]), "+f"(d[3])
                        : "r"(a[mi][0]), "r"(a[mi][1]), "r"(a[mi][2]), "r"(a[mi][3]),
                          "r"(b[nb][sub * 2]), "r"(b[nb][sub * 2 + 1]));
                }
    }
}

__device__ void sim_block(uint32_t sb, char* smem, int tileIdx,
                          const float* __restrict__ log_tau) {
    const int tid  = threadIdx.x;
    const int wid  = tid >> 5;
    const int lane = tid & 31;
    const int row0 = (tileIdx >> 5) * 128;
    const int col0 = (tileIdx & 31) * 128;
    const int warpM = (wid >> 1) * 32;
    const int warpN = (wid & 1) * 64;

    const char* qa = (const char*)(g_qb + (size_t)row0 * DIM);
    const char* pa = (const char*)(g_pb + (size_t)col0 * DIM);

    float acc[2][8][4];
    #pragma unroll
    for (int mi = 0; mi < 2; mi++)
        #pragma unroll
        for (int ni = 0; ni < 8; ni++)
            #pragma unroll
            for (int r = 0; r < 4; r++) acc[mi][ni][r] = 0.f;

    load_chunk(sb, qa, pa, 0, 0, tid); CP_COMMIT();
    load_chunk(sb, qa, pa, 1, 1, tid); CP_COMMIT();

    asm volatile("cp.async.wait_group 1;" ::: "memory");
    __syncthreads();
    compute_chunk(sb, 0, warpM, warpN, lane, acc);
    __syncthreads();
    load_chunk(sb, qa, pa, 2, 0, tid); CP_COMMIT();

    asm volatile("cp.async.wait_group 1;" ::: "memory");
    __syncthreads();
    compute_chunk(sb, 1, warpM, warpN, lane, acc);
    __syncthreads();
    load_chunk(sb, qa, pa, 3, 1, tid); CP_COMMIT();

    asm volatile("cp.async.wait_group 1;" ::: "memory");
    __syncthreads();
    compute_chunk(sb, 0, warpM, warpN, lane, acc);

    asm volatile("cp.async.wait_group 0;" ::: "memory");
    __syncthreads();
    compute_chunk(sb, 1, warpM, warpN, lane, acc);

    // ---- epilogue ----
    const float scale = inv_tau(log_tau);
    const int g   = lane >> 2;
    const int tig = lane & 3;
    const bool diagBlk = (row0 == col0);

    float rsum[4];
    #pragma unroll
    for (int k = 0; k < 4; k++) rsum[k] = 0.f;
    float csum[8][2];
    #pragma unroll
    for (int ni = 0; ni < 8; ni++) { csum[ni][0] = 0.f; csum[ni][1] = 0.f; }

    #pragma unroll
    for (int mi = 0; mi < 2; mi++)
        #pragma unroll
        for (int ni = 0; ni < 8; ni++)
            #pragma unroll
            for (int r = 0; r < 4; r++) {
                int h = r >> 1, c = r & 1;
                float v = acc[mi][ni][r] * scale;
                if (diagBlk) {
                    int lr = warpM + mi * 16 + h * 8 + g;
                    int lc = warpN + ni * 8 + tig * 2 + c;
                    if (lr == lc) g_diag[row0 + lr] = v;
                }
                float e = __expf(v);
                rsum[mi * 2 + h] += e;
                csum[ni][c] += e;
            }

    #pragma unroll
    for (int k = 0; k < 4; k++) {
        rsum[k] += __shfl_xor_sync(0xffffffffu, rsum[k], 1);
        rsum[k] += __shfl_xor_sync(0xffffffffu, rsum[k], 2);
    }
    if (tig == 0) {
        #pragma unroll
        for (int k = 0; k < 4; k++) {
            int lr = warpM + (k >> 1) * 16 + (k & 1) * 8 + g;
            atomicAdd(&g_rowsum[row0 + lr], rsum[k]);
        }
    }
    #pragma unroll
    for (int ni = 0; ni < 8; ni++)
        #pragma unroll
        for (int c = 0; c < 2; c++) {
            csum[ni][c] += __shfl_xor_sync(0xffffffffu, csum[ni][c], 4);
            csum[ni][c] += __shfl_xor_sync(0xffffffffu, csum[ni][c], 8);
            csum[ni][c] += __shfl_xor_sync(0xffffffffu, csum[ni][c], 16);
        }
    if (lane < 4) {
        #pragma unroll
        for (int ni = 0; ni < 8; ni++)
            #pragma unroll
            for (int c = 0; c < 2; c++) {
                int lc = warpN + ni * 8 + lane * 2 + c;
                atomicAdd(&g_colsum[col0 + lc], csum[ni][c]);
            }
    }
}

// neg block: 32 negatives, 8 threads each; per-thread 16 front-batched LDG.128.
__device__ void neg_block(int negBlk, const float* __restrict__ q,
                          const float* __restrict__ nem,
                          const float* __restrict__ log_tau) {
    const int tid = threadIdx.x;
    const int neg = negBlk * 32 + (tid >> 3);
    const int l8  = tid & 7;

    const int qid = g_qid[neg];
    const float4* nr = (const float4*)(nem + (size_t)neg * DIM);
    const float4* qr = (const float4*)(q   + (size_t)qid * DIM);

    float4 nv[8], qv[8];
    #pragma unroll
    for (int j = 0; j < 8; j++) nv[j] = nr[l8 + j * 8];
    #pragma unroll
    for (int j = 0; j < 8; j++) qv[j] = qr[l8 + j * 8];

    float dot = 0.f;
    #pragma unroll
    for (int j = 0; j < 8; j++)
        dot += qv[j].x * nv[j].x + qv[j].y * nv[j].y
             + qv[j].z * nv[j].z + qv[j].w * nv[j].w;
    dot += __shfl_xor_sync(0xffffffffu, dot, 1);
    dot += __shfl_xor_sync(0xffffffffu, dot, 2);
    dot += __shfl_xor_sync(0xffffffffu, dot, 4);
    if (l8 == 0)
        atomicAdd(&g_negsum[qid], __expf(dot * inv_tau(log_tau)));
}

__global__ __launch_bounds__(256, 2)
void fused_kernel(const float* __restrict__ q, const float* __restrict__ nem,
                  const float* __restrict__ log_tau)
{
    extern __shared__ char smem[];
    const int bid = blockIdx.x;
    if (bid & 1) {
        neg_block(bid >> 1, q, nem, log_tau);
    } else {
        sim_block(smem_u32(smem), smem, bid >> 1, log_tau);
    }
}

// ---------------- finalize ----------------
__global__ void finalize_kernel(float* __restrict__ out) {
    __shared__ float sh[256];
    int tid = threadIdx.x;
    float s = 0.f;
    for (int i = tid; i < BATCH; i += 256) {
        float d  = g_diag[i];
        float lq = logf(g_rowsum[i] + g_negsum[i]) - d;
        float lp = logf(g_colsum[i]) - d;
        s += 0.5f * (lq + lp);
    }
    sh[tid] = s;
    __syncthreads();
    #pragma unroll
    for (int off = 128; off >= 32; off >>= 1) {
        if (tid < off) sh[tid] += sh[tid + off];
        __syncthreads();
    }
    if (tid < 32) {
        float v = sh[tid];
        #pragma unroll
        for (int m = 16; m >= 1; m >>= 1)
            v += __shfl_xor_sync(0xffffffffu, v, m);
        if (tid == 0) out[0] = v / (float)BATCH;
    }
}

extern "C" void kernel_launch(void* const* d_in, const int* in_sizes, int n_in,
                              void* d_out, int out_size) {
    const float* q   = (const float*)d_in[0];
    const float* p   = (const float*)d_in[1];
    const float* nem = (const float*)d_in[2];
    const int*   cnt = (const int*)  d_in[3];
    const float* lt  = (const float*)d_in[4];
    float* out = (float*)d_out;

    cudaFuncSetAttribute(fused_kernel,
                         cudaFuncAttributeMaxDynamicSharedMemorySize, SM_TOTAL);

    convert_scan_kernel<<<1025, 256>>>(q, p, cnt);
    fused_kernel<<<2048, 256, SM_TOTAL>>>(q, nem, lt);
    finalize_kernel<<<1, 256>>>(out);
}

// round 6
// speedup vs baseline: 4.3524x; 1.2286x over previous
#include <cuda_runtime.h>
#include <cuda_bf16.h>
#include <cstdint>

#define BATCH 4096
#define DIM   256
#define NNEG  32768

// ---------------- scratch (device globals; no allocs allowed) ----------------
__device__ float g_rowsum[BATCH];
__device__ float g_colsum[BATCH];
__device__ float g_negsum[BATCH];
__device__ float g_diag[BATCH];
__device__ int   g_off[BATCH];          // exclusive prefix of counts
__device__ __nv_bfloat16 g_qb[BATCH * DIM];
__device__ __nv_bfloat16 g_pb[BATCH * DIM];

__device__ __forceinline__ uint32_t smem_u32(const void* p) {
    uint32_t a;
    asm("{ .reg .u64 t; cvta.to.shared.u64 t, %1; cvt.u32.u64 %0, t; }" : "=r"(a) : "l"(p));
    return a;
}

__device__ __forceinline__ float inv_tau(const float* log_tau) {
    float t = expf(log_tau[0]);
    t = fminf(fmaxf(t, 1e-4f), 1.0f);
    return 1.0f / t;
}

// ---------------- setup: fp32->bf16 convert + zero + (block 1024) offsets scan ----------------
// Blocks 0..1023: 256 threads convert. Block 1024: 1024 threads scan offsets only.
__global__ void convert_scan_kernel(const float* __restrict__ q, const float* __restrict__ p,
                                    const int* __restrict__ counts) {
    int tid = threadIdx.x;
    if (blockIdx.x < 1024) {
        if (tid >= 256) return;
        int i = blockIdx.x * 256 + tid;  // over BATCH*DIM/4
        if (i < BATCH) { g_rowsum[i] = 0.f; g_colsum[i] = 0.f; g_negsum[i] = 0.f; }
        const float4 qa = ((const float4*)q)[i];
        const float4 pa = ((const float4*)p)[i];
        __nv_bfloat162* qd = (__nv_bfloat162*)g_qb;
        __nv_bfloat162* pd = (__nv_bfloat162*)g_pb;
        qd[i * 2 + 0] = __floats2bfloat162_rn(qa.x, qa.y);
        qd[i * 2 + 1] = __floats2bfloat162_rn(qa.z, qa.w);
        pd[i * 2 + 0] = __floats2bfloat162_rn(pa.x, pa.y);
        pd[i * 2 + 1] = __floats2bfloat162_rn(pa.z, pa.w);
        return;
    }
    // ---- scan block: offsets only, fully parallel ----
    __shared__ int wsum[32];
    int lane = tid & 31, w = tid >> 5;
    int4 c4 = ((const int4*)counts)[tid];          // counts[4t .. 4t+3]
    int run = c4.x + c4.y + c4.z + c4.w;
    int incl = run;
    #pragma unroll
    for (int m = 1; m < 32; m <<= 1) {
        int t = __shfl_up_sync(0xffffffffu, incl, m);
        if (lane >= m) incl += t;
    }
    if (lane == 31) wsum[w] = incl;
    __syncthreads();
    if (tid < 32) {
        int v = wsum[tid];
        int s = v;
        #pragma unroll
        for (int m = 1; m < 32; m <<= 1) {
            int t = __shfl_up_sync(0xffffffffu, s, m);
            if (tid >= m) s += t;
        }
        wsum[tid] = s - v;   // exclusive warp base
    }
    __syncthreads();
    int excl = incl - run + wsum[w];
    int4 o;
    o.x = excl;
    o.y = o.x + c4.x;
    o.z = o.y + c4.y;
    o.w = o.z + c4.z;
    ((int4*)g_off)[tid] = o;
}

// ---------------- fused sim(MMA) + neg kernel ----------------
// Even blockIdx -> sim 128x128 tile; odd blockIdx -> 32 negatives.
#define STRIDE     144
#define TILE_BYTES (128 * STRIDE)
#define BUF_BYTES  (2 * TILE_BYTES)
#define SM_TOTAL   (2 * BUF_BYTES)     // 73728

#define CP_COMMIT() asm volatile("cp.async.commit_group;" ::: "memory")

__device__ __forceinline__ void load_chunk(uint32_t sb, const char* qa, const char* pa,
                                           int chunk, int buf, int tid) {
    uint32_t base = sb + buf * BUF_BYTES;
    #pragma unroll
    for (int it = 0; it < 4; it++) {
        int idx = it * 256 + tid;
        int r = idx >> 3, s = idx & 7;
        uint32_t dst = base + r * STRIDE + s * 16;
        const char* srcA = qa + r * 512 + chunk * 128 + s * 16;
        const char* srcB = pa + r * 512 + chunk * 128 + s * 16;
        asm volatile("cp.async.cg.shared.global [%0], [%1], 16;" :: "r"(dst), "l"(srcA));
        asm volatile("cp.async.cg.shared.global [%0], [%1], 16;"
                     :: "r"(dst + TILE_BYTES), "l"(srcB));
    }
}

__device__ __forceinline__ void compute_chunk(uint32_t sb, int buf, int warpM, int warpN,
                                              int lane, float acc[2][8][4]) {
    uint32_t base  = sb + buf * BUF_BYTES;
    uint32_t aAddr = base + (uint32_t)(warpM + (lane & 15)) * STRIDE
                   + (uint32_t)(lane >> 4) * 16;
    uint32_t bAddr = base + TILE_BYTES
                   + (uint32_t)(warpN + (lane & 7) + ((lane >> 4) << 3)) * STRIDE
                   + (uint32_t)((lane >> 3) & 1) * 16;
    #pragma unroll
    for (int s = 0; s < 4; s++) {
        const uint32_t koff = (uint32_t)s * 32;
        uint32_t a[2][4];
        #pragma unroll
        for (int mi = 0; mi < 2; mi++) {
            asm volatile("ldmatrix.sync.aligned.m8n8.x4.shared.b16 {%0,%1,%2,%3}, [%4];"
                : "=r"(a[mi][0]), "=r"(a[mi][1]), "=r"(a[mi][2]), "=r"(a[mi][3])
                : "r"(aAddr + mi * (16 * STRIDE) + koff));
        }
        uint32_t b[4][4];
        #pragma unroll
        for (int nb = 0; nb < 4; nb++) {
            asm volatile("ldmatrix.sync.aligned.m8n8.x4.shared.b16 {%0,%1,%2,%3}, [%4];"
                : "=r"(b[nb][0]), "=r"(b[nb][1]), "=r"(b[nb][2]), "=r"(b[nb][3])
                : "r"(bAddr + nb * (16 * STRIDE) + koff));
        }
        #pragma unroll
        for (int mi = 0; mi < 2; mi++)
            #pragma unroll
            for (int nb = 0; nb < 4; nb++)
                #pragma unroll
                for (int sub = 0; sub < 2; sub++) {
                    float* d = acc[mi][nb * 2 + sub];
                    asm volatile(
                        "mma.sync.aligned.m16n8k16.row.col.f32.bf16.bf16.f32 "
                        "{%0,%1,%2,%3}, {%4,%5,%6,%7}, {%8,%9}, {%0,%1,%2,%3};"
                        : "+f"(d[0]), "+f"(d[1]), "+f"(d[2]), "+f"(d[3])
                        : "r"(a[mi][0]), "r"(a[mi][1]), "r"(a[mi][2]), "r"(a[mi][3]),
                          "r"(b[nb][sub * 2]), "r"(b[nb][sub * 2 + 1]));
                }
    }
}

__device__ void sim_block(uint32_t sb, int tileIdx, const float* __restrict__ log_tau) {
    const int tid  = threadIdx.x;
    const int wid  = tid >> 5;
    const int lane = tid & 31;
    const int row0 = (tileIdx >> 5) * 128;
    const int col0 = (tileIdx & 31) * 128;
    const int warpM = (wid >> 1) * 32;
    const int warpN = (wid & 1) * 64;

    const char* qa = (const char*)(g_qb + (size_t)row0 * DIM);
    const char* pa = (const char*)(g_pb + (size_t)col0 * DIM);

    float acc[2][8][4];
    #pragma unroll
    for (int mi = 0; mi < 2; mi++)
        #pragma unroll
        for (int ni = 0; ni < 8; ni++)
            #pragma unroll
            for (int r = 0; r < 4; r++) acc[mi][ni][r] = 0.f;

    load_chunk(sb, qa, pa, 0, 0, tid); CP_COMMIT();
    load_chunk(sb, qa, pa, 1, 1, tid); CP_COMMIT();

    asm volatile("cp.async.wait_group 1;" ::: "memory");
    __syncthreads();
    compute_chunk(sb, 0, warpM, warpN, lane, acc);
    __syncthreads();
    load_chunk(sb, qa, pa, 2, 0, tid); CP_COMMIT();

    asm volatile("cp.async.wait_group 1;" ::: "memory");
    __syncthreads();
    compute_chunk(sb, 1, warpM, warpN, lane, acc);
    __syncthreads();
    load_chunk(sb, qa, pa, 3, 1, tid); CP_COMMIT();

    asm volatile("cp.async.wait_group 1;" ::: "memory");
    __syncthreads();
    compute_chunk(sb, 0, warpM, warpN, lane, acc);

    asm volatile("cp.async.wait_group 0;" ::: "memory");
    __syncthreads();
    compute_chunk(sb, 1, warpM, warpN, lane, acc);

    // ---- epilogue ----
    const float scale = inv_tau(log_tau);
    const int g   = lane >> 2;
    const int tig = lane & 3;
    const bool diagBlk = (row0 == col0);

    float rsum[4];
    #pragma unroll
    for (int k = 0; k < 4; k++) rsum[k] = 0.f;
    float csum[8][2];
    #pragma unroll
    for (int ni = 0; ni < 8; ni++) { csum[ni][0] = 0.f; csum[ni][1] = 0.f; }

    #pragma unroll
    for (int mi = 0; mi < 2; mi++)
        #pragma unroll
        for (int ni = 0; ni < 8; ni++)
            #pragma unroll
            for (int r = 0; r < 4; r++) {
                int h = r >> 1, c = r & 1;
                float v = acc[mi][ni][r] * scale;
                if (diagBlk) {
                    int lr = warpM + mi * 16 + h * 8 + g;
                    int lc = warpN + ni * 8 + tig * 2 + c;
                    if (lr == lc) g_diag[row0 + lr] = v;
                }
                float e = __expf(v);
                rsum[mi * 2 + h] += e;
                csum[ni][c] += e;
            }

    #pragma unroll
    for (int k = 0; k < 4; k++) {
        rsum[k] += __shfl_xor_sync(0xffffffffu, rsum[k], 1);
        rsum[k] += __shfl_xor_sync(0xffffffffu, rsum[k], 2);
    }
    if (tig == 0) {
        #pragma unroll
        for (int k = 0; k < 4; k++) {
            int lr = warpM + (k >> 1) * 16 + (k & 1) * 8 + g;
            atomicAdd(&g_rowsum[row0 + lr], rsum[k]);
        }
    }
    #pragma unroll
    for (int ni = 0; ni < 8; ni++)
        #pragma unroll
        for (int c = 0; c < 2; c++) {
            csum[ni][c] += __shfl_xor_sync(0xffffffffu, csum[ni][c], 4);
            csum[ni][c] += __shfl_xor_sync(0xffffffffu, csum[ni][c], 8);
            csum[ni][c] += __shfl_xor_sync(0xffffffffu, csum[ni][c], 16);
        }
    if (lane < 4) {
        #pragma unroll
        for (int ni = 0; ni < 8; ni++)
            #pragma unroll
            for (int c = 0; c < 2; c++) {
                int lc = warpN + ni * 8 + lane * 2 + c;
                atomicAdd(&g_colsum[col0 + lc], csum[ni][c]);
            }
    }
}

// neg block: 32 negatives, 8 threads each; qid via binary search on g_off.
__device__ void neg_block(int negBlk, const float* __restrict__ q,
                          const float* __restrict__ nem,
                          const float* __restrict__ log_tau) {
    const int tid = threadIdx.x;
    const int neg = negBlk * 32 + (tid >> 3);
    const int l8  = tid & 7;

    // qid = max{ i : g_off[i] <= neg }  (12-step binary search, table L1/L2-hot)
    int lo = 0, hi = BATCH - 1;
    #pragma unroll
    for (int it = 0; it < 12; it++) {
        int mid = (lo + hi + 1) >> 1;
        if (__ldg(&g_off[mid]) <= neg) lo = mid; else hi = mid - 1;
    }
    const int qid = lo;

    const float4* nr = (const float4*)(nem + (size_t)neg * DIM);
    const float4* qr = (const float4*)(q   + (size_t)qid * DIM);

    float4 nv[8], qv[8];
    #pragma unroll
    for (int j = 0; j < 8; j++) nv[j] = nr[l8 + j * 8];
    #pragma unroll
    for (int j = 0; j < 8; j++) qv[j] = qr[l8 + j * 8];

    float dot = 0.f;
    #pragma unroll
    for (int j = 0; j < 8; j++)
        dot += qv[j].x * nv[j].x + qv[j].y * nv[j].y
             + qv[j].z * nv[j].z + qv[j].w * nv[j].w;
    dot += __shfl_xor_sync(0xffffffffu, dot, 1);
    dot += __shfl_xor_sync(0xffffffffu, dot, 2);
    dot += __shfl_xor_sync(0xffffffffu, dot, 4);
    if (l8 == 0)
        atomicAdd(&g_negsum[qid], __expf(dot * inv_tau(log_tau)));
}

__global__ __launch_bounds__(256, 2)
void fused_kernel(const float* __restrict__ q, const float* __restrict__ nem,
                  const float* __restrict__ log_tau)
{
    extern __shared__ char smem[];
    const int bid = blockIdx.x;
    if (bid & 1) {
        neg_block(bid >> 1, q, nem, log_tau);
    } else {
        sim_block(smem_u32(smem), bid >> 1, log_tau);
    }
}

// ---------------- finalize ----------------
__global__ void finalize_kernel(float* __restrict__ out) {
    __shared__ float sh[256];
    int tid = threadIdx.x;
    float s = 0.f;
    for (int i = tid; i < BATCH; i += 256) {
        float d  = g_diag[i];
        float lq = logf(g_rowsum[i] + g_negsum[i]) - d;
        float lp = logf(g_colsum[i]) - d;
        s += 0.5f * (lq + lp);
    }
    sh[tid] = s;
    __syncthreads();
    #pragma unroll
    for (int off = 128; off >= 32; off >>= 1) {
        if (tid < off) sh[tid] += sh[tid + off];
        __syncthreads();
    }
    if (tid < 32) {
        float v = sh[tid];
        #pragma unroll
        for (int m = 16; m >= 1; m >>= 1)
            v += __shfl_xor_sync(0xffffffffu, v, m);
        if (tid == 0) out[0] = v / (float)BATCH;
    }
}

extern "C" void kernel_launch(void* const* d_in, const int* in_sizes, int n_in,
                              void* d_out, int out_size) {
    const float* q   = (const float*)d_in[0];
    const float* p   = (const float*)d_in[1];
    const float* nem = (const float*)d_in[2];
    const int*   cnt = (const int*)  d_in[3];
    const float* lt  = (const float*)d_in[4];
    float* out = (float*)d_out;

    cudaFuncSetAttribute(fused_kernel,
                         cudaFuncAttributeMaxDynamicSharedMemorySize, SM_TOTAL);

    convert_scan_kernel<<<1025, 1024>>>(q, p, cnt);
    fused_kernel<<<2048, 256, SM_TOTAL>>>(q, nem, lt);
    finalize_kernel<<<1, 256>>>(out);
}